// round 14
// baseline (speedup 1.0000x reference)
#include <cuda_runtime.h>
#include <cuda_bf16.h>
#include <cstdint>

#define FEAT 39
#define HID 1024
#define SEQ 254
#define NCLS 10
#define FC1N 100
#define BATCH 128

// Scratch (device globals; no allocation allowed).
__device__ float g_seq[SEQ * BATCH * HID];        // xproj then h_s, in place (fp32)
__device__ float g_part[2 * SEQ * BATCH * FC1N];  // FC1 split-K partials (2-way k-split)
__device__ float g_h1[BATCH * FC1N];
__device__ unsigned g_flag[4][SEQ][32];           // per-block step-publish flags (130 KB)
// full-sequence h in bf16 hi/lo; slot s+1 holds h_s, slot 0 holds h0.
__device__ __nv_bfloat16 g_hseq[SEQ + 1][2][BATCH][HID];  // 134 MB

// ---------------- helpers ----------------
__device__ __forceinline__ unsigned smem_u32(const void* p) {
    return (unsigned)__cvta_generic_to_shared(p);
}
__device__ __forceinline__ void unpack2(unsigned long long v, float& lo, float& hi) {
    asm("mov.b64 {%0, %1}, %2;" : "=f"(lo), "=f"(hi) : "l"(v));
}
__device__ __forceinline__ void fma2(unsigned long long& d, unsigned long long a,
                                     unsigned long long b) {
    asm("fma.rn.f32x2 %0, %1, %2, %0;" : "+l"(d) : "l"(a), "l"(b));
}
__device__ __forceinline__ unsigned long long lds64(unsigned addr) {
    unsigned long long r;
    asm volatile("ld.shared.b64 %0, [%1];" : "=l"(r) : "r"(addr));
    return r;
}
__device__ __forceinline__ void cpasync16(unsigned dst, const void* src) {
    asm volatile("cp.async.cg.shared.global [%0], [%1], 16;" ::"r"(dst), "l"(src));
}
__device__ __forceinline__ void cp_commit() {
    asm volatile("cp.async.commit_group;");
}
template <int N>
__device__ __forceinline__ void cp_wait() {
    asm volatile("cp.async.wait_group %0;" ::"n"(N));
}
__device__ __forceinline__ void ldsm4(unsigned* r, unsigned addr) {
    asm volatile("ldmatrix.sync.aligned.m8n8.x4.shared.b16 {%0,%1,%2,%3}, [%4];"
                 : "=r"(r[0]), "=r"(r[1]), "=r"(r[2]), "=r"(r[3])
                 : "r"(addr));
}
__device__ __forceinline__ void mma16816(float* d, const unsigned* a, unsigned b0,
                                         unsigned b1) {
    asm volatile(
        "mma.sync.aligned.m16n8k16.row.col.f32.bf16.bf16.f32 "
        "{%0,%1,%2,%3}, {%4,%5,%6,%7}, {%8,%9}, {%0,%1,%2,%3};"
        : "+f"(d[0]), "+f"(d[1]), "+f"(d[2]), "+f"(d[3])
        : "r"(a[0]), "r"(a[1]), "r"(a[2]), "r"(a[3]), "r"(b0), "r"(b1));
}
__device__ __forceinline__ void st_release(unsigned* p, unsigned v) {
    asm volatile("st.release.gpu.global.u32 [%0], %1;" ::"l"(p), "r"(v) : "memory");
}
// warp-parallel flag wait: lane j watches flag[j]; exits when all 32 are set
__device__ __forceinline__ void poll_flags(const unsigned* base, int lane) {
    unsigned v;
    asm volatile("ld.acquire.gpu.global.u32 %0, [%1];" : "=r"(v) : "l"(base + lane));
    while (__any_sync(0xFFFFFFFFu, v == 0u)) {
        __nanosleep(20);
        asm volatile("ld.acquire.gpu.global.u32 %0, [%1];" : "=r"(v) : "l"(base + lane));
    }
}
__device__ __forceinline__ float tanh_fast(float x) {
    float r;
    asm("tanh.approx.f32 %0, %1;" : "=f"(r) : "f"(x));
    return r;
}
__device__ __forceinline__ unsigned bf16x2pack(float lo, float hi) {
    unsigned r;
    asm("cvt.rn.bf16x2.f32 %0, %1, %2;" : "=r"(r) : "f"(hi), "f"(lo));
    return r;
}
__device__ __forceinline__ float bf16lo_as_f32(unsigned p) {
    return __bfloat162float(__ushort_as_bfloat16((unsigned short)(p & 0xFFFFu)));
}
__device__ __forceinline__ float bf16hi_as_f32(unsigned p) {
    return __bfloat162float(__ushort_as_bfloat16((unsigned short)(p >> 16)));
}

// ---------------- kernel 1: xproj = x @ W_ih^T + b_ih + b_hh, time-major ----------------
#define XP_BM 64
#define XP_BN 64
#define XP_PAD 41
__global__ __launch_bounds__(256) void xproj_kernel(
    const float* __restrict__ x, const float* __restrict__ Wih,
    const float* __restrict__ bih, const float* __restrict__ bhh) {
    __shared__ float Xs[XP_BM][XP_PAD];
    __shared__ float Ws[XP_BN][XP_PAD];
    int t = threadIdx.x;
    int n0 = blockIdx.x * XP_BN;
    int r0 = blockIdx.y * XP_BM;

    for (int i = t; i < XP_BM * FEAT; i += 256) {
        int row = i / FEAT, col = i % FEAT;
        int r = r0 + row;
        int b = r & (BATCH - 1), s = r >> 7;
        Xs[row][col] = x[((size_t)b * SEQ + s) * FEAT + col];
    }
    for (int i = t; i < XP_BN * FEAT; i += 256) {
        int row = i / FEAT, col = i % FEAT;
        Ws[row][col] = Wih[(size_t)(n0 + row) * FEAT + col];
    }
    __syncthreads();

    int tn = t & 15, tm = t >> 4;
    float acc[4][4] = {};
#pragma unroll
    for (int k = 0; k < FEAT; k++) {
        float a[4], w[4];
#pragma unroll
        for (int i = 0; i < 4; i++) a[i] = Xs[tm * 4 + i][k];
#pragma unroll
        for (int j = 0; j < 4; j++) w[j] = Ws[tn * 4 + j][k];
#pragma unroll
        for (int i = 0; i < 4; i++)
#pragma unroll
            for (int j = 0; j < 4; j++) acc[i][j] += a[i] * w[j];
    }
#pragma unroll
    for (int j = 0; j < 4; j++) {
        int n = n0 + tn * 4 + j;
        float bias = bih[n] + bhh[n];
#pragma unroll
        for (int i = 0; i < 4; i++) {
            int r = r0 + tm * 4 + i;
            g_seq[(size_t)r * HID + n] = acc[i][j] + bias;
        }
    }
}

// ---------------- kernel 1b: h0 -> bf16 hi/lo (slot 0), zero flags ----------------
__global__ __launch_bounds__(256) void h0cvt_kernel(const float* __restrict__ h0) {
    int idx = blockIdx.x * 256 + threadIdx.x;
    if (idx < 4 * SEQ * 32) ((unsigned*)g_flag)[idx] = 0u;
    if (idx >= BATCH * HID) return;
    int m = idx >> 10, n = idx & 1023;
    float v = h0[idx];
    __nv_bfloat16 hi = __float2bfloat16(v);
    __nv_bfloat16 lo = __float2bfloat16(v - __bfloat162float(hi));
    g_hseq[0][0][m][n] = hi;
    g_hseq[0][1][m][n] = lo;
}

// ---------------- kernel 2: PERSISTENT DUAL-PIPE recurrence scan ----------------
// 128 blocks = (32 nj) x (4 mi), 256 thr (8 warps), 1 block/SM, all resident.
// Warps 0-3: HMMA (tensor pipe) on k in [w*128, w*128+128), W resident bf16 hi/lo.
// Warps 4-7: fma2 (fma pipe)   on k in [w*128, w*128+128), W resident fp32.
// Step sync: distinct-address release flags per block + warp-parallel acquire
// polls (no atomic contention, no trailing block barrier).
#define WB_HI 0                 // bf16 hi W: 32n x 512k, row stride 1040 B
#define WB_LO 33280
#define WF_OFF 66560            // fp32 W: 32n x 512k, row stride 2080 B
#define ABH_OFF 133120          // HMMA A tiles: 4 warps x [2 buf][2 split][32 x 80B]
#define AF_OFF 174080           // fma2 A tiles: 4 warps x [2 buf][32 x 36 floats]
#define SCAN_SMEM 210944
#define RS_STRIDE 36            // floats per Rs row (float4-aligned)

__global__ __launch_bounds__(256) void rnn_dual(const float* __restrict__ h0,
                                                const float* __restrict__ Whh) {
    extern __shared__ unsigned char smc[];
    unsigned smBase = smem_u32(smc);
    int t = threadIdx.x;
    int nj = blockIdx.x, mi = blockIdx.y;
    int n0 = nj * 32, m0 = mi * 32;
    int w = t >> 5, l = t & 31;
    int thrm = l >> 2, thrn = l & 3;
    int srow0 = l >> 2, sc4 = l & 3;

    // ---- load resident W (once): bf16 hi/lo for k<512, fp32 for k>=512 ----
    for (int idx = t; idx < 32 * 512; idx += 256) {
        int r = idx >> 9, k = idx & 511;
        float v = Whh[(size_t)(n0 + r) * HID + k];
        __nv_bfloat16 hi = __float2bfloat16(v);
        __nv_bfloat16 lo = __float2bfloat16(v - __bfloat162float(hi));
        *(__nv_bfloat16*)(smc + WB_HI + r * 1040 + k * 2) = hi;
        *(__nv_bfloat16*)(smc + WB_LO + r * 1040 + k * 2) = lo;
    }
    for (int idx = t * 4; idx < 32 * 512; idx += 1024) {
        int r = idx >> 9, k = idx & 511;
        float4 v = *(const float4*)(Whh + (size_t)(n0 + r) * HID + 512 + k);
        *(float4*)(smc + WF_OFF + r * 2080 + k * 4) = v;
    }
    __syncthreads();

    // role-invariant addresses
    unsigned abBase = smBase + ABH_OFF + (unsigned)(w * 10240);           // HMMA (w<4)
    unsigned aLane = (unsigned)((l & 15) * 80 + (l >> 4) * 16);
    unsigned bLane = (unsigned)(((l >> 4) * 8 + (l & 7)) * 1040 + ((l >> 3) & 1) * 16);
    unsigned afBase = smBase + AF_OFF + (unsigned)((w - 4) * 9216);       // fma2 (w>=4)
    unsigned aOff[4], wOff[8];
#pragma unroll
    for (int i = 0; i < 4; i++) aOff[i] = (unsigned)((thrm + 8 * i) * 144);
#pragma unroll
    for (int j = 0; j < 8; j++) wOff[j] = (unsigned)(WF_OFF + (thrn + 4 * j) * 2080);

    float* Rs = (float*)(smc + ABH_OFF);  // [8][32][36] reduction scratch (aliases A)
    int mE = t >> 3;                      // epilogue row 0..31
    int nqE = (t & 7) * 4;                // epilogue col quad

    for (int s = 0; s < SEQ; s++) {
        const float* Hp = (s == 0) ? h0 : (g_seq + (size_t)(s - 1) * BATCH * HID);
        float* outp = g_seq + (size_t)s * BATCH * HID;

        // dataflow gate: wait for all 32 producers of step s-1 (warp-parallel)
        if (s > 0) poll_flags(&g_flag[mi][s - 1][0], l);

        // prefetch this step's xproj quad (retires under the mainloop)
        float* gpE = outp + (size_t)(m0 + mE) * HID + (n0 + nqE);
        float4 xpE = *(const float4*)gpE;

        float accH[2][4][4];
        unsigned long long accF[4][8];

        if (w < 4) {
            // =================== HMMA role ===================
#pragma unroll
            for (int a = 0; a < 2; a++)
#pragma unroll
                for (int b = 0; b < 4; b++)
#pragma unroll
                    for (int c = 0; c < 4; c++) accH[a][b][c] = 0.0f;

            auto stageH = [&](int c, int buf) {
                int kbase = w * 128 + c * 32;
                unsigned dst = abBase + (unsigned)(buf * 5120 + l * 80);
                const __nv_bfloat16* s0 = &g_hseq[s][0][m0 + l][kbase];
                const __nv_bfloat16* s1 = &g_hseq[s][1][m0 + l][kbase];
#pragma unroll
                for (int q = 0; q < 4; q++) {
                    cpasync16(dst + q * 16u, s0 + q * 8);
                    cpasync16(dst + 2560u + q * 16u, s1 + q * 8);
                }
                cp_commit();
            };
            auto compH = [&](int c, int buf) {
                unsigned aB = abBase + (unsigned)(buf * 5120) + aLane;
                unsigned bB = smBase + (unsigned)(WB_HI + w * 256 + c * 64) + bLane;
#pragma unroll
                for (int kk = 0; kk < 2; kk++) {
                    unsigned ah[2][4], al[2][4], bh[2][4], bl[2][4];
#pragma unroll
                    for (int hh = 0; hh < 2; hh++) {
                        ldsm4(ah[hh], aB + (unsigned)(hh * 1280 + kk * 32));
                        ldsm4(al[hh], aB + (unsigned)(2560 + hh * 1280 + kk * 32));
                    }
#pragma unroll
                    for (int nh = 0; nh < 2; nh++) {
                        ldsm4(bh[nh], bB + (unsigned)(nh * 16640 + kk * 32));
                        ldsm4(bl[nh], bB + (unsigned)(33280 + nh * 16640 + kk * 32));
                    }
#pragma unroll
                    for (int hh = 0; hh < 2; hh++)
#pragma unroll
                        for (int nh = 0; nh < 2; nh++) {
                            mma16816(accH[hh][nh * 2 + 0], ah[hh], bh[nh][0], bh[nh][1]);
                            mma16816(accH[hh][nh * 2 + 0], ah[hh], bl[nh][0], bl[nh][1]);
                            mma16816(accH[hh][nh * 2 + 0], al[hh], bh[nh][0], bh[nh][1]);
                            mma16816(accH[hh][nh * 2 + 1], ah[hh], bh[nh][2], bh[nh][3]);
                            mma16816(accH[hh][nh * 2 + 1], ah[hh], bl[nh][2], bl[nh][3]);
                            mma16816(accH[hh][nh * 2 + 1], al[hh], bh[nh][2], bh[nh][3]);
                        }
                }
            };
            stageH(0, 0);
            stageH(1, 1);
            cp_wait<1>();
            __syncwarp();
            compH(0, 0);
            stageH(2, 0);
            cp_wait<1>();
            __syncwarp();
            compH(1, 1);
            stageH(3, 1);
            cp_wait<1>();
            __syncwarp();
            compH(2, 0);
            cp_wait<0>();
            __syncwarp();
            compH(3, 1);
        } else {
            // =================== fma2 role ===================
#pragma unroll
            for (int i = 0; i < 4; i++)
#pragma unroll
                for (int j = 0; j < 8; j++) accF[i][j] = 0ull;

            auto stageF = [&](int c, int buf) {
                int kbase = w * 128 + c * 32;
#pragma unroll
                for (int q = 0; q < 8; q++) {
                    int row = srow0 + 8 * (q & 3);
                    int c4 = sc4 + 4 * (q >> 2);
                    unsigned dst = afBase + (unsigned)(buf * 4608 + (row * 36 + c4 * 4) * 4);
                    cpasync16(dst, Hp + (size_t)(m0 + row) * HID + kbase + c4 * 4);
                }
                cp_commit();
            };
            auto compF = [&](int c, int buf) {
                unsigned aB = afBase + (unsigned)(buf * 4608);
                unsigned wK = smBase + (unsigned)(((w * 128 - 512) + c * 32) * 4);
#pragma unroll
                for (int kp = 0; kp < 16; kp++) {
                    unsigned kByte = (unsigned)kp * 8u;
                    unsigned long long a[4], wv[8];
#pragma unroll
                    for (int i = 0; i < 4; i++) a[i] = lds64(aB + aOff[i] + kByte);
#pragma unroll
                    for (int j = 0; j < 8; j++) wv[j] = lds64(wK + wOff[j] + kByte);
#pragma unroll
                    for (int i = 0; i < 4; i++)
#pragma unroll
                        for (int j = 0; j < 8; j++) fma2(accF[i][j], a[i], wv[j]);
                }
            };
            stageF(0, 0);
            stageF(1, 1);
            cp_wait<1>();
            __syncwarp();
            compF(0, 0);
            stageF(2, 0);
            cp_wait<1>();
            __syncwarp();
            compF(1, 1);
            stageF(3, 1);
            cp_wait<1>();
            __syncwarp();
            compF(2, 0);
            cp_wait<0>();
            __syncwarp();
            compF(3, 1);
        }

        __syncthreads();  // all warps done with A staging before aliasing as Rs

        // ---- write warp partials into Rs ----
        if (w < 4) {
#pragma unroll
            for (int hh = 0; hh < 2; hh++)
#pragma unroll
                for (int j = 0; j < 4; j++) {
                    int mrow = hh * 16 + (l >> 2);
                    int nc = j * 8 + 2 * (l & 3);
                    *(float2*)&Rs[(w * 32 + mrow) * RS_STRIDE + nc] =
                        make_float2(accH[hh][j][0], accH[hh][j][1]);
                    *(float2*)&Rs[(w * 32 + mrow + 8) * RS_STRIDE + nc] =
                        make_float2(accH[hh][j][2], accH[hh][j][3]);
                }
        } else {
#pragma unroll
            for (int i = 0; i < 4; i++) {
                int m = thrm + 8 * i;
#pragma unroll
                for (int j = 0; j < 8; j++) {
                    int n = thrn + 4 * j;
                    float lo, hi;
                    unpack2(accF[i][j], lo, hi);
                    Rs[(w * 32 + m) * RS_STRIDE + n] = lo + hi;
                }
            }
        }
        __syncthreads();

        // ---- vectorized reduce + prefetched xp + tanh.approx ----
        {
            float4 sum = make_float4(0.f, 0.f, 0.f, 0.f);
#pragma unroll
            for (int g = 0; g < 8; g++) {
                float4 v = *(float4*)&Rs[(g * 32 + mE) * RS_STRIDE + nqE];
                sum.x += v.x;
                sum.y += v.y;
                sum.z += v.z;
                sum.w += v.w;
            }
            float4 h;
            h.x = tanh_fast(xpE.x + sum.x);
            h.y = tanh_fast(xpE.y + sum.y);
            h.z = tanh_fast(xpE.z + sum.z);
            h.w = tanh_fast(xpE.w + sum.w);
            *(float4*)gpE = h;

            unsigned p01 = bf16x2pack(h.x, h.y);
            unsigned p23 = bf16x2pack(h.z, h.w);
            float r0 = h.x - bf16lo_as_f32(p01);
            float r1 = h.y - bf16hi_as_f32(p01);
            float r2 = h.z - bf16lo_as_f32(p23);
            float r3 = h.w - bf16hi_as_f32(p23);
            unsigned q01 = bf16x2pack(r0, r1);
            unsigned q23 = bf16x2pack(r2, r3);
            *(uint2*)&g_hseq[s + 1][0][m0 + mE][n0 + nqE] = make_uint2(p01, p23);
            *(uint2*)&g_hseq[s + 1][1][m0 + mE][n0 + nqE] = make_uint2(q01, q23);
        }

        __syncthreads();  // all h writes block-visible & program-ordered before release
        if (t == 0) st_release(&g_flag[mi][s][nj], 1u);
        // no trailing barrier: each warp self-gates on next step's poll
    }
}

// ---------------- kernel 3: FC1 as 3-term bf16 HMMA GEMM ----------------
#define F1_B_OFF 0                      // B tiles: [2 buf][2 split][112 x 80B]
#define F1_BBUF 17920
#define F1_BSPL 8960
#define F1_A_OFF 35840                  // A: [8 warps][2 buf][2 split][16 x 80B]
#define F1_AWARP 5120
#define F1_W_OFF 76800                  // W stage fp32: [2 buf][104 x 144B]
#define F1_WBUF 14976
#define F1_SMEM 106752

__global__ __launch_bounds__(256, 2) void fc1_hmma(const float* __restrict__ W1) {
    extern __shared__ unsigned char smc[];
    unsigned smBase = smem_u32(smc);
    int s = blockIdx.x;
    int kh = blockIdx.y;  // k-half 0..1
    int t = threadIdx.x;
    int w = t >> 5, l = t & 31;
    int khbase = kh * 512;

    // zero pad rows 104..111 of all 4 B regions (once)
    for (int i = t; i < 640; i += 256) {
        int reg = i / 160, off = (i % 160) * 4;
        int b = reg >> 1, sp = reg & 1;
        *(unsigned*)(smc + F1_B_OFF + b * F1_BBUF + sp * F1_BSPL + 104 * 80 + off) = 0u;
    }
    __syncthreads();

    unsigned aLane = (unsigned)((l & 15) * 80 + (l >> 4) * 16);
    unsigned bLane = (unsigned)(((l >> 4) * 8 + (l & 7)) * 80 + ((l >> 3) & 1) * 16);
    unsigned aWarp = smBase + (unsigned)(F1_A_OFF + w * F1_AWARP);

    auto stage = [&](int c) {
        int buf = c & 1;
        int kc = khbase + c * 32;
#pragma unroll
        for (int sp = 0; sp < 2; sp++) {
#pragma unroll
            for (int q = 0; q < 2; q++) {
                int idx = l + q * 32;
                int row = idx >> 2, seg = idx & 3;
                cpasync16(aWarp + (unsigned)(buf * 2560 + sp * 1280 + row * 80 + seg * 16),
                          &g_hseq[s + 1][sp][w * 16 + row][kc + seg * 8]);
            }
        }
        for (int i = t; i < 832; i += 256) {
            int row = i >> 3, seg = i & 7;
            if (row < FC1N)
                cpasync16(smBase + (unsigned)(F1_W_OFF + buf * F1_WBUF + row * 144 + seg * 16),
                          W1 + (size_t)row * (SEQ * HID) + (size_t)s * HID + kc + seg * 4);
        }
        cp_commit();
    };

    auto convert = [&](int c) {
        int buf = c & 1;
        const unsigned char* ws = smc + F1_W_OFF + buf * F1_WBUF;
        unsigned char* bhi = smc + F1_B_OFF + buf * F1_BBUF;
        unsigned char* blo = bhi + F1_BSPL;
        for (int i = t; i < 832; i += 256) {
            int row = i >> 3, q = i & 7;
            float4 v = (row < FC1N) ? *(const float4*)(ws + row * 144 + q * 16)
                                    : make_float4(0.f, 0.f, 0.f, 0.f);
            unsigned p0 = bf16x2pack(v.x, v.y);
            unsigned p1 = bf16x2pack(v.z, v.w);
            float r0 = v.x - bf16lo_as_f32(p0);
            float r1 = v.y - bf16hi_as_f32(p0);
            float r2 = v.z - bf16lo_as_f32(p1);
            float r3 = v.w - bf16hi_as_f32(p1);
            unsigned q0 = bf16x2pack(r0, r1);
            unsigned q1 = bf16x2pack(r2, r3);
            *(uint2*)(bhi + row * 80 + q * 8) = make_uint2(p0, p1);
            *(uint2*)(blo + row * 80 + q * 8) = make_uint2(q0, q1);
        }
    };

    float acc[14][4];
#pragma unroll
    for (int j = 0; j < 14; j++)
#pragma unroll
        for (int c = 0; c < 4; c++) acc[j][c] = 0.0f;

    auto compute = [&](int c) {
        int buf = c & 1;
        unsigned aB = aWarp + (unsigned)(buf * 2560) + aLane;
        unsigned bB = smBase + (unsigned)(F1_B_OFF + buf * F1_BBUF) + bLane;
#pragma unroll
        for (int kk = 0; kk < 2; kk++) {
            unsigned ah[4], al[4];
            ldsm4(ah, aB + (unsigned)(kk * 32));
            ldsm4(al, aB + (unsigned)(1280 + kk * 32));
#pragma unroll
            for (int jt = 0; jt < 7; jt++) {
                unsigned bh[4], bl[4];
                ldsm4(bh, bB + (unsigned)(jt * 1280 + kk * 32));
                ldsm4(bl, bB + (unsigned)(F1_BSPL + jt * 1280 + kk * 32));
                mma16816(acc[2 * jt + 0], ah, bh[0], bh[1]);
                mma16816(acc[2 * jt + 0], ah, bl[0], bl[1]);
                mma16816(acc[2 * jt + 0], al, bh[0], bh[1]);
                mma16816(acc[2 * jt + 1], ah, bh[2], bh[3]);
                mma16816(acc[2 * jt + 1], ah, bl[2], bl[3]);
                mma16816(acc[2 * jt + 1], al, bh[2], bh[3]);
            }
        }
    };

    stage(0);
    stage(1);
#pragma unroll 1
    for (int c = 0; c < 16; c++) {
        if (c >= 14) cp_wait<0>(); else cp_wait<1>();
        __syncthreads();
        convert(c);
        __syncthreads();
        compute(c);
        if (c < 14) stage(c + 2);
    }

    float* dst = g_part + ((size_t)kh * SEQ + s) * BATCH * FC1N;
    int b0 = w * 16 + (l >> 2);
#pragma unroll
    for (int nt = 0; nt < 13; nt++) {
        int f0 = 8 * nt + 2 * (l & 3);
        if (f0 < FC1N) {
            *(float2*)&dst[(size_t)b0 * FC1N + f0] = make_float2(acc[nt][0], acc[nt][1]);
            *(float2*)&dst[(size_t)(b0 + 8) * FC1N + f0] = make_float2(acc[nt][2], acc[nt][3]);
        }
    }
}

// ---------------- kernel 4: deterministic reduce + bias + relu ----------------
__global__ __launch_bounds__(256) void reduce_kernel(const float* __restrict__ b1) {
    int i = blockIdx.x * 256 + threadIdx.x;
    if (i >= BATCH * FC1N) return;
    int f = i % FC1N;
    float p0 = 0.0f, p1 = 0.0f;
    for (int q = 0; q < 2 * SEQ; q += 2) {
        p0 += g_part[(size_t)q * BATCH * FC1N + i];
        p1 += g_part[(size_t)(q + 1) * BATCH * FC1N + i];
    }
    g_h1[i] = fmaxf(b1[f] + p0 + p1, 0.0f);
}

// ---------------- kernel 5: FC2 + log_softmax ----------------
__global__ __launch_bounds__(128) void fc2_kernel(const float* __restrict__ W2,
                                                  const float* __restrict__ b2,
                                                  float* __restrict__ out) {
    __shared__ float sW2[NCLS * FC1N];
    int t = threadIdx.x;
    for (int i = t; i < NCLS * FC1N; i += 128) sW2[i] = W2[i];
    __syncthreads();

    float hv[FC1N];
#pragma unroll
    for (int f = 0; f < FC1N; f++) hv[f] = g_h1[(size_t)t * FC1N + f];

    float logits[NCLS];
#pragma unroll
    for (int c = 0; c < NCLS; c++) {
        float acc = b2[c];
#pragma unroll
        for (int f = 0; f < FC1N; f++) acc += hv[f] * sW2[c * FC1N + f];
        logits[c] = acc;
    }
    float m = logits[0];
#pragma unroll
    for (int c = 1; c < NCLS; c++) m = fmaxf(m, logits[c]);
    float sum = 0.0f;
#pragma unroll
    for (int c = 0; c < NCLS; c++) sum += expf(logits[c] - m);
    float lse = m + logf(sum);
#pragma unroll
    for (int c = 0; c < NCLS; c++) out[(size_t)t * NCLS + c] = logits[c] - lse;
}

// ---------------- launch ----------------
extern "C" void kernel_launch(void* const* d_in, const int* in_sizes, int n_in,
                              void* d_out, int out_size) {
    const float* x = (const float*)d_in[0];
    const float* h0 = (const float*)d_in[1];
    const float* Wih = (const float*)d_in[2];
    const float* Whh = (const float*)d_in[3];
    const float* bih = (const float*)d_in[4];
    const float* bhh = (const float*)d_in[5];
    const float* W1 = (const float*)d_in[6];
    const float* b1 = (const float*)d_in[7];
    const float* W2 = (const float*)d_in[8];
    const float* b2 = (const float*)d_in[9];
    float* out = (float*)d_out;
    (void)in_sizes; (void)n_in; (void)out_size;

    cudaFuncSetAttribute(rnn_dual, cudaFuncAttributeMaxDynamicSharedMemorySize,
                         SCAN_SMEM);
    cudaFuncSetAttribute(fc1_hmma, cudaFuncAttributeMaxDynamicSharedMemorySize,
                         F1_SMEM);

    xproj_kernel<<<dim3(HID / XP_BN, (SEQ * BATCH) / XP_BM), 256>>>(x, Wih, bih, bhh);
    h0cvt_kernel<<<(BATCH * HID + 255) / 256, 256>>>(h0);
    rnn_dual<<<dim3(32, 4), 256, SCAN_SMEM>>>(h0, Whh);
    fc1_hmma<<<dim3(SEQ, 2), 256, F1_SMEM>>>(W1);
    reduce_kernel<<<(BATCH * FC1N + 255) / 256, 256>>>(b1);
    fc2_kernel<<<1, 128>>>(W2, b2, out);
}

// round 15
// speedup vs baseline: 1.0678x; 1.0678x over previous
#include <cuda_runtime.h>
#include <cuda_bf16.h>
#include <cstdint>

#define FEAT 39
#define HID 1024
#define SEQ 254
#define NCLS 10
#define FC1N 100
#define BATCH 128

// Scratch (device globals; no allocation allowed).
__device__ float g_seq[SEQ * BATCH * HID];        // xproj then h_s, in place (fp32)
__device__ float g_part[2 * SEQ * BATCH * FC1N];  // FC1 split-K partials (2-way k-split)
__device__ float g_h1[BATCH * FC1N];
__device__ unsigned g_flag[4][SEQ][32];           // per-block step-publish flags (130 KB)
// full-sequence h in bf16 hi/lo; slot s+1 holds h_s, slot 0 holds h0.
__device__ __nv_bfloat16 g_hseq[SEQ + 1][2][BATCH][HID];  // 134 MB

// ---------------- helpers ----------------
__device__ __forceinline__ unsigned smem_u32(const void* p) {
    return (unsigned)__cvta_generic_to_shared(p);
}
__device__ __forceinline__ void unpack2(unsigned long long v, float& lo, float& hi) {
    asm("mov.b64 {%0, %1}, %2;" : "=f"(lo), "=f"(hi) : "l"(v));
}
__device__ __forceinline__ void fma2(unsigned long long& d, unsigned long long a,
                                     unsigned long long b) {
    asm("fma.rn.f32x2 %0, %1, %2, %0;" : "+l"(d) : "l"(a), "l"(b));
}
__device__ __forceinline__ unsigned long long lds64(unsigned addr) {
    unsigned long long r;
    asm volatile("ld.shared.b64 %0, [%1];" : "=l"(r) : "r"(addr));
    return r;
}
__device__ __forceinline__ void cpasync16(unsigned dst, const void* src) {
    asm volatile("cp.async.cg.shared.global [%0], [%1], 16;" ::"r"(dst), "l"(src));
}
__device__ __forceinline__ void cp_commit() {
    asm volatile("cp.async.commit_group;");
}
template <int N>
__device__ __forceinline__ void cp_wait() {
    asm volatile("cp.async.wait_group %0;" ::"n"(N));
}
__device__ __forceinline__ void ldsm4(unsigned* r, unsigned addr) {
    asm volatile("ldmatrix.sync.aligned.m8n8.x4.shared.b16 {%0,%1,%2,%3}, [%4];"
                 : "=r"(r[0]), "=r"(r[1]), "=r"(r[2]), "=r"(r[3])
                 : "r"(addr));
}
__device__ __forceinline__ void mma16816(float* d, const unsigned* a, unsigned b0,
                                         unsigned b1) {
    asm volatile(
        "mma.sync.aligned.m16n8k16.row.col.f32.bf16.bf16.f32 "
        "{%0,%1,%2,%3}, {%4,%5,%6,%7}, {%8,%9}, {%0,%1,%2,%3};"
        : "+f"(d[0]), "+f"(d[1]), "+f"(d[2]), "+f"(d[3])
        : "r"(a[0]), "r"(a[1]), "r"(a[2]), "r"(a[3]), "r"(b0), "r"(b1));
}
__device__ __forceinline__ void st_release(unsigned* p, unsigned v) {
    asm volatile("st.release.gpu.global.u32 [%0], %1;" ::"l"(p), "r"(v) : "memory");
}
// warp-parallel flag wait: lane j watches flag[j]; exits when all 32 are set
__device__ __forceinline__ void poll_flags(const unsigned* base, int lane) {
    unsigned v;
    asm volatile("ld.acquire.gpu.global.u32 %0, [%1];" : "=r"(v) : "l"(base + lane));
    while (__any_sync(0xFFFFFFFFu, v == 0u)) {
        __nanosleep(30);
        asm volatile("ld.acquire.gpu.global.u32 %0, [%1];" : "=r"(v) : "l"(base + lane));
    }
}
__device__ __forceinline__ float tanh_fast(float x) {
    float r;
    asm("tanh.approx.f32 %0, %1;" : "=f"(r) : "f"(x));
    return r;
}
__device__ __forceinline__ unsigned bf16x2pack(float lo, float hi) {
    unsigned r;
    asm("cvt.rn.bf16x2.f32 %0, %1, %2;" : "=r"(r) : "f"(hi), "f"(lo));
    return r;
}
__device__ __forceinline__ float bf16lo_as_f32(unsigned p) {
    return __bfloat162float(__ushort_as_bfloat16((unsigned short)(p & 0xFFFFu)));
}
__device__ __forceinline__ float bf16hi_as_f32(unsigned p) {
    return __bfloat162float(__ushort_as_bfloat16((unsigned short)(p >> 16)));
}

// ---------------- kernel 1: xproj = x @ W_ih^T + b_ih + b_hh, time-major ----------------
#define XP_BM 64
#define XP_BN 64
#define XP_PAD 41
__global__ __launch_bounds__(256) void xproj_kernel(
    const float* __restrict__ x, const float* __restrict__ Wih,
    const float* __restrict__ bih, const float* __restrict__ bhh) {
    __shared__ float Xs[XP_BM][XP_PAD];
    __shared__ float Ws[XP_BN][XP_PAD];
    int t = threadIdx.x;
    int n0 = blockIdx.x * XP_BN;
    int r0 = blockIdx.y * XP_BM;

    for (int i = t; i < XP_BM * FEAT; i += 256) {
        int row = i / FEAT, col = i % FEAT;
        int r = r0 + row;
        int b = r & (BATCH - 1), s = r >> 7;
        Xs[row][col] = x[((size_t)b * SEQ + s) * FEAT + col];
    }
    for (int i = t; i < XP_BN * FEAT; i += 256) {
        int row = i / FEAT, col = i % FEAT;
        Ws[row][col] = Wih[(size_t)(n0 + row) * FEAT + col];
    }
    __syncthreads();

    int tn = t & 15, tm = t >> 4;
    float acc[4][4] = {};
#pragma unroll
    for (int k = 0; k < FEAT; k++) {
        float a[4], w[4];
#pragma unroll
        for (int i = 0; i < 4; i++) a[i] = Xs[tm * 4 + i][k];
#pragma unroll
        for (int j = 0; j < 4; j++) w[j] = Ws[tn * 4 + j][k];
#pragma unroll
        for (int i = 0; i < 4; i++)
#pragma unroll
            for (int j = 0; j < 4; j++) acc[i][j] += a[i] * w[j];
    }
#pragma unroll
    for (int j = 0; j < 4; j++) {
        int n = n0 + tn * 4 + j;
        float bias = bih[n] + bhh[n];
#pragma unroll
        for (int i = 0; i < 4; i++) {
            int r = r0 + tm * 4 + i;
            g_seq[(size_t)r * HID + n] = acc[i][j] + bias;
        }
    }
}

// ---------------- kernel 1b: h0 -> bf16 hi/lo (slot 0), zero flags ----------------
__global__ __launch_bounds__(256) void h0cvt_kernel(const float* __restrict__ h0) {
    int idx = blockIdx.x * 256 + threadIdx.x;
    if (idx < 4 * SEQ * 32) ((unsigned*)g_flag)[idx] = 0u;
    if (idx >= BATCH * HID) return;
    int m = idx >> 10, n = idx & 1023;
    float v = h0[idx];
    __nv_bfloat16 hi = __float2bfloat16(v);
    __nv_bfloat16 lo = __float2bfloat16(v - __bfloat162float(hi));
    g_hseq[0][0][m][n] = hi;
    g_hseq[0][1][m][n] = lo;
}

// ---------------- kernel 2: PERSISTENT DUAL-PIPE recurrence scan ----------------
// 128 blocks = (32 nj) x (4 mi), 256 thr (8 warps), 1 block/SM, all resident.
// Warps 0-3: HMMA (tensor pipe) on k in [w*128, w*128+128), W resident bf16 hi/lo.
// Warps 4-7: fma2 (fma pipe)   on k in [w*128, w*128+128), W resident fp32.
// Step gate (R13 structure, R14 addresses): each block publishes ONE release
// store to its own flag; warp 0 polls the 32 flags lane-parallel; trailing
// bar.sync keeps the block phase-locked. No atomic serialization, no 8x poll
// storm.
#define WB_HI 0                 // bf16 hi W: 32n x 512k, row stride 1040 B
#define WB_LO 33280
#define WF_OFF 66560            // fp32 W: 32n x 512k, row stride 2080 B
#define ABH_OFF 133120          // HMMA A tiles: 4 warps x [2 buf][2 split][32 x 80B]
#define AF_OFF 174080           // fma2 A tiles: 4 warps x [2 buf][32 x 36 floats]
#define SCAN_SMEM 210944
#define RS_STRIDE 36            // floats per Rs row (float4-aligned)

__global__ __launch_bounds__(256) void rnn_dual(const float* __restrict__ h0,
                                                const float* __restrict__ Whh) {
    extern __shared__ unsigned char smc[];
    unsigned smBase = smem_u32(smc);
    int t = threadIdx.x;
    int nj = blockIdx.x, mi = blockIdx.y;
    int n0 = nj * 32, m0 = mi * 32;
    int w = t >> 5, l = t & 31;
    int thrm = l >> 2, thrn = l & 3;
    int srow0 = l >> 2, sc4 = l & 3;

    // ---- load resident W (once): bf16 hi/lo for k<512, fp32 for k>=512 ----
    for (int idx = t; idx < 32 * 512; idx += 256) {
        int r = idx >> 9, k = idx & 511;
        float v = Whh[(size_t)(n0 + r) * HID + k];
        __nv_bfloat16 hi = __float2bfloat16(v);
        __nv_bfloat16 lo = __float2bfloat16(v - __bfloat162float(hi));
        *(__nv_bfloat16*)(smc + WB_HI + r * 1040 + k * 2) = hi;
        *(__nv_bfloat16*)(smc + WB_LO + r * 1040 + k * 2) = lo;
    }
    for (int idx = t * 4; idx < 32 * 512; idx += 1024) {
        int r = idx >> 9, k = idx & 511;
        float4 v = *(const float4*)(Whh + (size_t)(n0 + r) * HID + 512 + k);
        *(float4*)(smc + WF_OFF + r * 2080 + k * 4) = v;
    }
    __syncthreads();

    // role-invariant addresses
    unsigned abBase = smBase + ABH_OFF + (unsigned)(w * 10240);           // HMMA (w<4)
    unsigned aLane = (unsigned)((l & 15) * 80 + (l >> 4) * 16);
    unsigned bLane = (unsigned)(((l >> 4) * 8 + (l & 7)) * 1040 + ((l >> 3) & 1) * 16);
    unsigned afBase = smBase + AF_OFF + (unsigned)((w - 4) * 9216);       // fma2 (w>=4)
    unsigned aOff[4], wOff[8];
#pragma unroll
    for (int i = 0; i < 4; i++) aOff[i] = (unsigned)((thrm + 8 * i) * 144);
#pragma unroll
    for (int j = 0; j < 8; j++) wOff[j] = (unsigned)(WF_OFF + (thrn + 4 * j) * 2080);

    float* Rs = (float*)(smc + ABH_OFF);  // [8][32][36] reduction scratch (aliases A)
    int mE = t >> 3;                      // epilogue row 0..31
    int nqE = (t & 7) * 4;                // epilogue col quad

    for (int s = 0; s < SEQ; s++) {
        const float* Hp = (s == 0) ? h0 : (g_seq + (size_t)(s - 1) * BATCH * HID);
        float* outp = g_seq + (size_t)s * BATCH * HID;

        // prefetch this step's xproj quad (retires under the mainloop)
        float* gpE = outp + (size_t)(m0 + mE) * HID + (n0 + nqE);
        float4 xpE = *(const float4*)gpE;

        float accH[2][4][4];
        unsigned long long accF[4][8];

        if (w < 4) {
            // =================== HMMA role ===================
#pragma unroll
            for (int a = 0; a < 2; a++)
#pragma unroll
                for (int b = 0; b < 4; b++)
#pragma unroll
                    for (int c = 0; c < 4; c++) accH[a][b][c] = 0.0f;

            auto stageH = [&](int c, int buf) {
                int kbase = w * 128 + c * 32;
                unsigned dst = abBase + (unsigned)(buf * 5120 + l * 80);
                const __nv_bfloat16* s0 = &g_hseq[s][0][m0 + l][kbase];
                const __nv_bfloat16* s1 = &g_hseq[s][1][m0 + l][kbase];
#pragma unroll
                for (int q = 0; q < 4; q++) {
                    cpasync16(dst + q * 16u, s0 + q * 8);
                    cpasync16(dst + 2560u + q * 16u, s1 + q * 8);
                }
                cp_commit();
            };
            auto compH = [&](int c, int buf) {
                unsigned aB = abBase + (unsigned)(buf * 5120) + aLane;
                unsigned bB = smBase + (unsigned)(WB_HI + w * 256 + c * 64) + bLane;
#pragma unroll
                for (int kk = 0; kk < 2; kk++) {
                    unsigned ah[2][4], al[2][4], bh[2][4], bl[2][4];
#pragma unroll
                    for (int hh = 0; hh < 2; hh++) {
                        ldsm4(ah[hh], aB + (unsigned)(hh * 1280 + kk * 32));
                        ldsm4(al[hh], aB + (unsigned)(2560 + hh * 1280 + kk * 32));
                    }
#pragma unroll
                    for (int nh = 0; nh < 2; nh++) {
                        ldsm4(bh[nh], bB + (unsigned)(nh * 16640 + kk * 32));
                        ldsm4(bl[nh], bB + (unsigned)(33280 + nh * 16640 + kk * 32));
                    }
#pragma unroll
                    for (int hh = 0; hh < 2; hh++)
#pragma unroll
                        for (int nh = 0; nh < 2; nh++) {
                            mma16816(accH[hh][nh * 2 + 0], ah[hh], bh[nh][0], bh[nh][1]);
                            mma16816(accH[hh][nh * 2 + 0], ah[hh], bl[nh][0], bl[nh][1]);
                            mma16816(accH[hh][nh * 2 + 0], al[hh], bh[nh][0], bh[nh][1]);
                            mma16816(accH[hh][nh * 2 + 1], ah[hh], bh[nh][2], bh[nh][3]);
                            mma16816(accH[hh][nh * 2 + 1], ah[hh], bl[nh][2], bl[nh][3]);
                            mma16816(accH[hh][nh * 2 + 1], al[hh], bh[nh][2], bh[nh][3]);
                        }
                }
            };
            stageH(0, 0);
            stageH(1, 1);
            cp_wait<1>();
            __syncwarp();
            compH(0, 0);
            stageH(2, 0);
            cp_wait<1>();
            __syncwarp();
            compH(1, 1);
            stageH(3, 1);
            cp_wait<1>();
            __syncwarp();
            compH(2, 0);
            cp_wait<0>();
            __syncwarp();
            compH(3, 1);
        } else {
            // =================== fma2 role ===================
#pragma unroll
            for (int i = 0; i < 4; i++)
#pragma unroll
                for (int j = 0; j < 8; j++) accF[i][j] = 0ull;

            auto stageF = [&](int c, int buf) {
                int kbase = w * 128 + c * 32;
#pragma unroll
                for (int q = 0; q < 8; q++) {
                    int row = srow0 + 8 * (q & 3);
                    int c4 = sc4 + 4 * (q >> 2);
                    unsigned dst = afBase + (unsigned)(buf * 4608 + (row * 36 + c4 * 4) * 4);
                    cpasync16(dst, Hp + (size_t)(m0 + row) * HID + kbase + c4 * 4);
                }
                cp_commit();
            };
            auto compF = [&](int c, int buf) {
                unsigned aB = afBase + (unsigned)(buf * 4608);
                unsigned wK = smBase + (unsigned)(((w * 128 - 512) + c * 32) * 4);
#pragma unroll
                for (int kp = 0; kp < 16; kp++) {
                    unsigned kByte = (unsigned)kp * 8u;
                    unsigned long long a[4], wv[8];
#pragma unroll
                    for (int i = 0; i < 4; i++) a[i] = lds64(aB + aOff[i] + kByte);
#pragma unroll
                    for (int j = 0; j < 8; j++) wv[j] = lds64(wK + wOff[j] + kByte);
#pragma unroll
                    for (int i = 0; i < 4; i++)
#pragma unroll
                        for (int j = 0; j < 8; j++) fma2(accF[i][j], a[i], wv[j]);
                }
            };
            stageF(0, 0);
            stageF(1, 1);
            cp_wait<1>();
            __syncwarp();
            compF(0, 0);
            stageF(2, 0);
            cp_wait<1>();
            __syncwarp();
            compF(1, 1);
            stageF(3, 1);
            cp_wait<1>();
            __syncwarp();
            compF(2, 0);
            cp_wait<0>();
            __syncwarp();
            compF(3, 1);
        }

        __syncthreads();  // all warps done with A staging before aliasing as Rs

        // ---- write warp partials into Rs ----
        if (w < 4) {
#pragma unroll
            for (int hh = 0; hh < 2; hh++)
#pragma unroll
                for (int j = 0; j < 4; j++) {
                    int mrow = hh * 16 + (l >> 2);
                    int nc = j * 8 + 2 * (l & 3);
                    *(float2*)&Rs[(w * 32 + mrow) * RS_STRIDE + nc] =
                        make_float2(accH[hh][j][0], accH[hh][j][1]);
                    *(float2*)&Rs[(w * 32 + mrow + 8) * RS_STRIDE + nc] =
                        make_float2(accH[hh][j][2], accH[hh][j][3]);
                }
        } else {
#pragma unroll
            for (int i = 0; i < 4; i++) {
                int m = thrm + 8 * i;
#pragma unroll
                for (int j = 0; j < 8; j++) {
                    int n = thrn + 4 * j;
                    float lo, hi;
                    unpack2(accF[i][j], lo, hi);
                    Rs[(w * 32 + m) * RS_STRIDE + n] = lo + hi;
                }
            }
        }
        __syncthreads();

        // ---- vectorized reduce + prefetched xp + tanh.approx ----
        {
            float4 sum = make_float4(0.f, 0.f, 0.f, 0.f);
#pragma unroll
            for (int g = 0; g < 8; g++) {
                float4 v = *(float4*)&Rs[(g * 32 + mE) * RS_STRIDE + nqE];
                sum.x += v.x;
                sum.y += v.y;
                sum.z += v.z;
                sum.w += v.w;
            }
            float4 h;
            h.x = tanh_fast(xpE.x + sum.x);
            h.y = tanh_fast(xpE.y + sum.y);
            h.z = tanh_fast(xpE.z + sum.z);
            h.w = tanh_fast(xpE.w + sum.w);
            *(float4*)gpE = h;

            unsigned p01 = bf16x2pack(h.x, h.y);
            unsigned p23 = bf16x2pack(h.z, h.w);
            float r0 = h.x - bf16lo_as_f32(p01);
            float r1 = h.y - bf16hi_as_f32(p01);
            float r2 = h.z - bf16lo_as_f32(p23);
            float r3 = h.w - bf16hi_as_f32(p23);
            unsigned q01 = bf16x2pack(r0, r1);
            unsigned q23 = bf16x2pack(r2, r3);
            *(uint2*)&g_hseq[s + 1][0][m0 + mE][n0 + nqE] = make_uint2(p01, p23);
            *(uint2*)&g_hseq[s + 1][1][m0 + mE][n0 + nqE] = make_uint2(q01, q23);
        }

        __syncthreads();  // all h writes block-visible & program-ordered before release
        if (w == 0) {
            if (l == 0) st_release(&g_flag[mi][s][nj], 1u);
            if (s < SEQ - 1) poll_flags(&g_flag[mi][s][0], l);  // lane-parallel wait
        }
        __syncthreads();  // whole block proceeds once the m-group has published
    }
}

// ---------------- kernel 3: FC1 as 3-term bf16 HMMA GEMM ----------------
#define F1_B_OFF 0                      // B tiles: [2 buf][2 split][112 x 80B]
#define F1_BBUF 17920
#define F1_BSPL 8960
#define F1_A_OFF 35840                  // A: [8 warps][2 buf][2 split][16 x 80B]
#define F1_AWARP 5120
#define F1_W_OFF 76800                  // W stage fp32: [2 buf][104 x 144B]
#define F1_WBUF 14976
#define F1_SMEM 106752

__global__ __launch_bounds__(256, 2) void fc1_hmma(const float* __restrict__ W1) {
    extern __shared__ unsigned char smc[];
    unsigned smBase = smem_u32(smc);
    int s = blockIdx.x;
    int kh = blockIdx.y;  // k-half 0..1
    int t = threadIdx.x;
    int w = t >> 5, l = t & 31;
    int khbase = kh * 512;

    // zero pad rows 104..111 of all 4 B regions (once)
    for (int i = t; i < 640; i += 256) {
        int reg = i / 160, off = (i % 160) * 4;
        int b = reg >> 1, sp = reg & 1;
        *(unsigned*)(smc + F1_B_OFF + b * F1_BBUF + sp * F1_BSPL + 104 * 80 + off) = 0u;
    }
    __syncthreads();

    unsigned aLane = (unsigned)((l & 15) * 80 + (l >> 4) * 16);
    unsigned bLane = (unsigned)(((l >> 4) * 8 + (l & 7)) * 80 + ((l >> 3) & 1) * 16);
    unsigned aWarp = smBase + (unsigned)(F1_A_OFF + w * F1_AWARP);

    auto stage = [&](int c) {
        int buf = c & 1;
        int kc = khbase + c * 32;
#pragma unroll
        for (int sp = 0; sp < 2; sp++) {
#pragma unroll
            for (int q = 0; q < 2; q++) {
                int idx = l + q * 32;
                int row = idx >> 2, seg = idx & 3;
                cpasync16(aWarp + (unsigned)(buf * 2560 + sp * 1280 + row * 80 + seg * 16),
                          &g_hseq[s + 1][sp][w * 16 + row][kc + seg * 8]);
            }
        }
        for (int i = t; i < 832; i += 256) {
            int row = i >> 3, seg = i & 7;
            if (row < FC1N)
                cpasync16(smBase + (unsigned)(F1_W_OFF + buf * F1_WBUF + row * 144 + seg * 16),
                          W1 + (size_t)row * (SEQ * HID) + (size_t)s * HID + kc + seg * 4);
        }
        cp_commit();
    };

    auto convert = [&](int c) {
        int buf = c & 1;
        const unsigned char* ws = smc + F1_W_OFF + buf * F1_WBUF;
        unsigned char* bhi = smc + F1_B_OFF + buf * F1_BBUF;
        unsigned char* blo = bhi + F1_BSPL;
        for (int i = t; i < 832; i += 256) {
            int row = i >> 3, q = i & 7;
            float4 v = (row < FC1N) ? *(const float4*)(ws + row * 144 + q * 16)
                                    : make_float4(0.f, 0.f, 0.f, 0.f);
            unsigned p0 = bf16x2pack(v.x, v.y);
            unsigned p1 = bf16x2pack(v.z, v.w);
            float r0 = v.x - bf16lo_as_f32(p0);
            float r1 = v.y - bf16hi_as_f32(p0);
            float r2 = v.z - bf16lo_as_f32(p1);
            float r3 = v.w - bf16hi_as_f32(p1);
            unsigned q0 = bf16x2pack(r0, r1);
            unsigned q1 = bf16x2pack(r2, r3);
            *(uint2*)(bhi + row * 80 + q * 8) = make_uint2(p0, p1);
            *(uint2*)(blo + row * 80 + q * 8) = make_uint2(q0, q1);
        }
    };

    float acc[14][4];
#pragma unroll
    for (int j = 0; j < 14; j++)
#pragma unroll
        for (int c = 0; c < 4; c++) acc[j][c] = 0.0f;

    auto compute = [&](int c) {
        int buf = c & 1;
        unsigned aB = aWarp + (unsigned)(buf * 2560) + aLane;
        unsigned bB = smBase + (unsigned)(F1_B_OFF + buf * F1_BBUF) + bLane;
#pragma unroll
        for (int kk = 0; kk < 2; kk++) {
            unsigned ah[4], al[4];
            ldsm4(ah, aB + (unsigned)(kk * 32));
            ldsm4(al, aB + (unsigned)(1280 + kk * 32));
#pragma unroll
            for (int jt = 0; jt < 7; jt++) {
                unsigned bh[4], bl[4];
                ldsm4(bh, bB + (unsigned)(jt * 1280 + kk * 32));
                ldsm4(bl, bB + (unsigned)(F1_BSPL + jt * 1280 + kk * 32));
                mma16816(acc[2 * jt + 0], ah, bh[0], bh[1]);
                mma16816(acc[2 * jt + 0], ah, bl[0], bl[1]);
                mma16816(acc[2 * jt + 0], al, bh[0], bh[1]);
                mma16816(acc[2 * jt + 1], ah, bh[2], bh[3]);
                mma16816(acc[2 * jt + 1], ah, bl[2], bl[3]);
                mma16816(acc[2 * jt + 1], al, bh[2], bh[3]);
            }
        }
    };

    stage(0);
    stage(1);
#pragma unroll 1
    for (int c = 0; c < 16; c++) {
        if (c >= 14) cp_wait<0>(); else cp_wait<1>();
        __syncthreads();
        convert(c);
        __syncthreads();
        compute(c);
        if (c < 14) stage(c + 2);
    }

    float* dst = g_part + ((size_t)kh * SEQ + s) * BATCH * FC1N;
    int b0 = w * 16 + (l >> 2);
#pragma unroll
    for (int nt = 0; nt < 13; nt++) {
        int f0 = 8 * nt + 2 * (l & 3);
        if (f0 < FC1N) {
            *(float2*)&dst[(size_t)b0 * FC1N + f0] = make_float2(acc[nt][0], acc[nt][1]);
            *(float2*)&dst[(size_t)(b0 + 8) * FC1N + f0] = make_float2(acc[nt][2], acc[nt][3]);
        }
    }
}

// ---------------- kernel 4: deterministic reduce + bias + relu ----------------
__global__ __launch_bounds__(256) void reduce_kernel(const float* __restrict__ b1) {
    int i = blockIdx.x * 256 + threadIdx.x;
    if (i >= BATCH * FC1N) return;
    int f = i % FC1N;
    float p0 = 0.0f, p1 = 0.0f;
    for (int q = 0; q < 2 * SEQ; q += 2) {
        p0 += g_part[(size_t)q * BATCH * FC1N + i];
        p1 += g_part[(size_t)(q + 1) * BATCH * FC1N + i];
    }
    g_h1[i] = fmaxf(b1[f] + p0 + p1, 0.0f);
}

// ---------------- kernel 5: FC2 + log_softmax ----------------
__global__ __launch_bounds__(128) void fc2_kernel(const float* __restrict__ W2,
                                                  const float* __restrict__ b2,
                                                  float* __restrict__ out) {
    __shared__ float sW2[NCLS * FC1N];
    int t = threadIdx.x;
    for (int i = t; i < NCLS * FC1N; i += 128) sW2[i] = W2[i];
    __syncthreads();

    float hv[FC1N];
#pragma unroll
    for (int f = 0; f < FC1N; f++) hv[f] = g_h1[(size_t)t * FC1N + f];

    float logits[NCLS];
#pragma unroll
    for (int c = 0; c < NCLS; c++) {
        float acc = b2[c];
#pragma unroll
        for (int f = 0; f < FC1N; f++) acc += hv[f] * sW2[c * FC1N + f];
        logits[c] = acc;
    }
    float m = logits[0];
#pragma unroll
    for (int c = 1; c < NCLS; c++) m = fmaxf(m, logits[c]);
    float sum = 0.0f;
#pragma unroll
    for (int c = 0; c < NCLS; c++) sum += expf(logits[c] - m);
    float lse = m + logf(sum);
#pragma unroll
    for (int c = 0; c < NCLS; c++) out[(size_t)t * NCLS + c] = logits[c] - lse;
}

// ---------------- launch ----------------
extern "C" void kernel_launch(void* const* d_in, const int* in_sizes, int n_in,
                              void* d_out, int out_size) {
    const float* x = (const float*)d_in[0];
    const float* h0 = (const float*)d_in[1];
    const float* Wih = (const float*)d_in[2];
    const float* Whh = (const float*)d_in[3];
    const float* bih = (const float*)d_in[4];
    const float* bhh = (const float*)d_in[5];
    const float* W1 = (const float*)d_in[6];
    const float* b1 = (const float*)d_in[7];
    const float* W2 = (const float*)d_in[8];
    const float* b2 = (const float*)d_in[9];
    float* out = (float*)d_out;
    (void)in_sizes; (void)n_in; (void)out_size;

    cudaFuncSetAttribute(rnn_dual, cudaFuncAttributeMaxDynamicSharedMemorySize,
                         SCAN_SMEM);
    cudaFuncSetAttribute(fc1_hmma, cudaFuncAttributeMaxDynamicSharedMemorySize,
                         F1_SMEM);

    xproj_kernel<<<dim3(HID / XP_BN, (SEQ * BATCH) / XP_BM), 256>>>(x, Wih, bih, bhh);
    h0cvt_kernel<<<(BATCH * HID + 255) / 256, 256>>>(h0);
    rnn_dual<<<dim3(32, 4), 256, SCAN_SMEM>>>(h0, Whh);
    fc1_hmma<<<dim3(SEQ, 2), 256, F1_SMEM>>>(W1);
    reduce_kernel<<<(BATCH * FC1N + 255) / 256, 256>>>(b1);
    fc2_kernel<<<1, 128>>>(W2, b2, out);
}

// round 16
// speedup vs baseline: 1.4565x; 1.3641x over previous
#include <cuda_runtime.h>
#include <cuda_bf16.h>
#include <cstdint>

#define FEAT 39
#define HID 1024
#define SEQ 254
#define NCLS 10
#define FC1N 100
#define BATCH 128

// Scratch (device globals; no allocation allowed).
__device__ float g_seq[SEQ * BATCH * HID];        // xproj then h_s, in place (fp32)
__device__ float g_part[2 * SEQ * BATCH * FC1N];  // FC1 split-K partials (2-way k-split)
__device__ float g_h1[BATCH * FC1N];
__device__ unsigned g_bar[4];                     // per-m-group step barriers
// full-sequence h in bf16 hi/lo; slot s+1 holds h_s, slot 0 holds h0.
__device__ __nv_bfloat16 g_hseq[SEQ + 1][2][BATCH][HID];  // 134 MB

// ---------------- helpers ----------------
__device__ __forceinline__ unsigned smem_u32(const void* p) {
    return (unsigned)__cvta_generic_to_shared(p);
}
__device__ __forceinline__ void unpack2(unsigned long long v, float& lo, float& hi) {
    asm("mov.b64 {%0, %1}, %2;" : "=f"(lo), "=f"(hi) : "l"(v));
}
__device__ __forceinline__ void fma2(unsigned long long& d, unsigned long long a,
                                     unsigned long long b) {
    asm("fma.rn.f32x2 %0, %1, %2, %0;" : "+l"(d) : "l"(a), "l"(b));
}
__device__ __forceinline__ unsigned long long lds64(unsigned addr) {
    unsigned long long r;
    asm volatile("ld.shared.b64 %0, [%1];" : "=l"(r) : "r"(addr));
    return r;
}
__device__ __forceinline__ void cpasync16(unsigned dst, const void* src) {
    asm volatile("cp.async.cg.shared.global [%0], [%1], 16;" ::"r"(dst), "l"(src));
}
__device__ __forceinline__ void cp_commit() {
    asm volatile("cp.async.commit_group;");
}
template <int N>
__device__ __forceinline__ void cp_wait() {
    asm volatile("cp.async.wait_group %0;" ::"n"(N));
}
__device__ __forceinline__ void ldsm4(unsigned* r, unsigned addr) {
    asm volatile("ldmatrix.sync.aligned.m8n8.x4.shared.b16 {%0,%1,%2,%3}, [%4];"
                 : "=r"(r[0]), "=r"(r[1]), "=r"(r[2]), "=r"(r[3])
                 : "r"(addr));
}
__device__ __forceinline__ void mma16816(float* d, const unsigned* a, unsigned b0,
                                         unsigned b1) {
    asm volatile(
        "mma.sync.aligned.m16n8k16.row.col.f32.bf16.bf16.f32 "
        "{%0,%1,%2,%3}, {%4,%5,%6,%7}, {%8,%9}, {%0,%1,%2,%3};"
        : "+f"(d[0]), "+f"(d[1]), "+f"(d[2]), "+f"(d[3])
        : "r"(a[0]), "r"(a[1]), "r"(a[2]), "r"(a[3]), "r"(b0), "r"(b1));
}
__device__ __forceinline__ unsigned ld_acq(const unsigned* p) {
    unsigned v;
    asm volatile("ld.acquire.gpu.global.u32 %0, [%1];" : "=r"(v) : "l"(p));
    return v;
}
__device__ __forceinline__ void red_release_add(unsigned* p, unsigned v) {
    asm volatile("red.release.gpu.global.add.u32 [%0], %1;" ::"l"(p), "r"(v) : "memory");
}
__device__ __forceinline__ float tanh_fast(float x) {
    float r;
    asm("tanh.approx.f32 %0, %1;" : "=f"(r) : "f"(x));
    return r;
}
__device__ __forceinline__ unsigned bf16x2pack(float lo, float hi) {
    unsigned r;
    asm("cvt.rn.bf16x2.f32 %0, %1, %2;" : "=r"(r) : "f"(hi), "f"(lo));
    return r;
}
__device__ __forceinline__ float bf16lo_as_f32(unsigned p) {
    return __bfloat162float(__ushort_as_bfloat16((unsigned short)(p & 0xFFFFu)));
}
__device__ __forceinline__ float bf16hi_as_f32(unsigned p) {
    return __bfloat162float(__ushort_as_bfloat16((unsigned short)(p >> 16)));
}

// ---------------- kernel 1: xproj = x @ W_ih^T + b_ih + b_hh, time-major ----------------
#define XP_BM 64
#define XP_BN 64
#define XP_PAD 41
__global__ __launch_bounds__(256) void xproj_kernel(
    const float* __restrict__ x, const float* __restrict__ Wih,
    const float* __restrict__ bih, const float* __restrict__ bhh) {
    __shared__ float Xs[XP_BM][XP_PAD];
    __shared__ float Ws[XP_BN][XP_PAD];
    int t = threadIdx.x;
    int n0 = blockIdx.x * XP_BN;
    int r0 = blockIdx.y * XP_BM;

    for (int i = t; i < XP_BM * FEAT; i += 256) {
        int row = i / FEAT, col = i % FEAT;
        int r = r0 + row;
        int b = r & (BATCH - 1), s = r >> 7;
        Xs[row][col] = x[((size_t)b * SEQ + s) * FEAT + col];
    }
    for (int i = t; i < XP_BN * FEAT; i += 256) {
        int row = i / FEAT, col = i % FEAT;
        Ws[row][col] = Wih[(size_t)(n0 + row) * FEAT + col];
    }
    __syncthreads();

    int tn = t & 15, tm = t >> 4;
    float acc[4][4] = {};
#pragma unroll
    for (int k = 0; k < FEAT; k++) {
        float a[4], w[4];
#pragma unroll
        for (int i = 0; i < 4; i++) a[i] = Xs[tm * 4 + i][k];
#pragma unroll
        for (int j = 0; j < 4; j++) w[j] = Ws[tn * 4 + j][k];
#pragma unroll
        for (int i = 0; i < 4; i++)
#pragma unroll
            for (int j = 0; j < 4; j++) acc[i][j] += a[i] * w[j];
    }
#pragma unroll
    for (int j = 0; j < 4; j++) {
        int n = n0 + tn * 4 + j;
        float bias = bih[n] + bhh[n];
#pragma unroll
        for (int i = 0; i < 4; i++) {
            int r = r0 + tm * 4 + i;
            g_seq[(size_t)r * HID + n] = acc[i][j] + bias;
        }
    }
}

// ---------------- kernel 1b: h0 -> bf16 hi/lo (slot 0), reset barriers ----------------
__global__ __launch_bounds__(256) void h0cvt_kernel(const float* __restrict__ h0) {
    int idx = blockIdx.x * 256 + threadIdx.x;
    if (idx < 4) g_bar[idx] = 0u;
    if (idx >= BATCH * HID) return;
    int m = idx >> 10, n = idx & 1023;
    float v = h0[idx];
    __nv_bfloat16 hi = __float2bfloat16(v);
    __nv_bfloat16 lo = __float2bfloat16(v - __bfloat162float(hi));
    g_hseq[0][0][m][n] = hi;
    g_hseq[0][1][m][n] = lo;
}

// ---------------- kernel 2: PERSISTENT DUAL-PIPE recurrence scan ----------------
// 128 blocks = (32 nj) x (4 mi), 256 thr (8 warps), 1 block/SM, all resident.
// REBALANCED k-split (pipe-balance: tensor rt32 vs fma rt3):
//   Warps 0-3 (HMMA): k in [w*192, w*192+192), 6 chunks of 32; W bf16 hi/lo.
//   Warps 4-7 (fma2): k in [768+(w-4)*64, +64), 2 chunks of 32; W fp32.
// Sync: R13's proven per-m-group monotonic counter (red.release + acquire poll).
#define WB_HI 0                 // bf16 hi W: 32n x 768k, row stride 1552 B
#define WB_ROWB 1552
#define WB_LO 49664
#define WF_OFF 99328            // fp32 W: 32n x 256k, row stride 1040 B
#define WF_ROWB 1040
#define ABH_OFF 132608          // HMMA A tiles: 4 warps x [2 buf][2 split][32 x 80B]
#define AF_OFF 173568           // fma2 A tiles: 4 warps x [2 buf][32 x 36 floats]
#define SCAN_SMEM 210432
#define RS_STRIDE 36            // floats per Rs row (float4-aligned)

__global__ __launch_bounds__(256) void rnn_dual(const float* __restrict__ h0,
                                                const float* __restrict__ Whh) {
    extern __shared__ unsigned char smc[];
    unsigned smBase = smem_u32(smc);
    int t = threadIdx.x;
    int nj = blockIdx.x, mi = blockIdx.y;
    int n0 = nj * 32, m0 = mi * 32;
    int w = t >> 5, l = t & 31;
    int thrm = l >> 2, thrn = l & 3;
    int srow0 = l >> 2, sc4 = l & 3;

    // ---- load resident W (once): bf16 hi/lo for k<768, fp32 for k>=768 ----
    for (int i = t; i < 32 * 768; i += 256) {
        int r = i / 768, k = i % 768;
        float v = Whh[(size_t)(n0 + r) * HID + k];
        __nv_bfloat16 hi = __float2bfloat16(v);
        __nv_bfloat16 lo = __float2bfloat16(v - __bfloat162float(hi));
        *(__nv_bfloat16*)(smc + WB_HI + r * WB_ROWB + k * 2) = hi;
        *(__nv_bfloat16*)(smc + WB_LO + r * WB_ROWB + k * 2) = lo;
    }
    for (int idx = t * 4; idx < 32 * 256; idx += 1024) {
        int r = idx >> 8, k = idx & 255;
        float4 v = *(const float4*)(Whh + (size_t)(n0 + r) * HID + 768 + k);
        *(float4*)(smc + WF_OFF + r * WF_ROWB + k * 4) = v;
    }
    __syncthreads();

    // role-invariant addresses
    unsigned abBase = smBase + ABH_OFF + (unsigned)(w * 10240);           // HMMA (w<4)
    unsigned aLane = (unsigned)((l & 15) * 80 + (l >> 4) * 16);
    unsigned bLane = (unsigned)(((l >> 4) * 8 + (l & 7)) * WB_ROWB + ((l >> 3) & 1) * 16);
    unsigned afBase = smBase + AF_OFF + (unsigned)((w - 4) * 9216);       // fma2 (w>=4)
    unsigned aOff[4], wOff[8];
#pragma unroll
    for (int i = 0; i < 4; i++) aOff[i] = (unsigned)((thrm + 8 * i) * 144);
#pragma unroll
    for (int j = 0; j < 8; j++) wOff[j] = (unsigned)(WF_OFF + (thrn + 4 * j) * WF_ROWB);

    float* Rs = (float*)(smc + ABH_OFF);  // [8][32][36] reduction scratch (aliases A)
    int mE = t >> 3;                      // epilogue row 0..31
    int nqE = (t & 7) * 4;                // epilogue col quad

    for (int s = 0; s < SEQ; s++) {
        const float* Hp = (s == 0) ? h0 : (g_seq + (size_t)(s - 1) * BATCH * HID);
        float* outp = g_seq + (size_t)s * BATCH * HID;

        // prefetch this step's xproj quad (retires under the mainloop)
        float* gpE = outp + (size_t)(m0 + mE) * HID + (n0 + nqE);
        float4 xpE = *(const float4*)gpE;

        float accH[2][4][4];
        unsigned long long accF[4][8];

        if (w < 4) {
            // =================== HMMA role: 6 chunks of 32 k ===================
#pragma unroll
            for (int a = 0; a < 2; a++)
#pragma unroll
                for (int b = 0; b < 4; b++)
#pragma unroll
                    for (int c = 0; c < 4; c++) accH[a][b][c] = 0.0f;

            auto stageH = [&](int c, int buf) {
                int kbase = w * 192 + c * 32;
                unsigned dst = abBase + (unsigned)(buf * 5120 + l * 80);
                const __nv_bfloat16* s0 = &g_hseq[s][0][m0 + l][kbase];
                const __nv_bfloat16* s1 = &g_hseq[s][1][m0 + l][kbase];
#pragma unroll
                for (int q = 0; q < 4; q++) {
                    cpasync16(dst + q * 16u, s0 + q * 8);
                    cpasync16(dst + 2560u + q * 16u, s1 + q * 8);
                }
                cp_commit();
            };
            auto compH = [&](int c, int buf) {
                unsigned aB = abBase + (unsigned)(buf * 5120) + aLane;
                unsigned bB = smBase + (unsigned)(WB_HI + w * 384 + c * 64) + bLane;
#pragma unroll
                for (int kk = 0; kk < 2; kk++) {
                    unsigned ah[2][4], al[2][4], bh[2][4], bl[2][4];
#pragma unroll
                    for (int hh = 0; hh < 2; hh++) {
                        ldsm4(ah[hh], aB + (unsigned)(hh * 1280 + kk * 32));
                        ldsm4(al[hh], aB + (unsigned)(2560 + hh * 1280 + kk * 32));
                    }
#pragma unroll
                    for (int nh = 0; nh < 2; nh++) {
                        ldsm4(bh[nh], bB + (unsigned)(nh * 16 * WB_ROWB + kk * 32));
                        ldsm4(bl[nh], bB + (unsigned)(WB_LO + nh * 16 * WB_ROWB + kk * 32));
                    }
#pragma unroll
                    for (int hh = 0; hh < 2; hh++)
#pragma unroll
                        for (int nh = 0; nh < 2; nh++) {
                            mma16816(accH[hh][nh * 2 + 0], ah[hh], bh[nh][0], bh[nh][1]);
                            mma16816(accH[hh][nh * 2 + 0], ah[hh], bl[nh][0], bl[nh][1]);
                            mma16816(accH[hh][nh * 2 + 0], al[hh], bh[nh][0], bh[nh][1]);
                            mma16816(accH[hh][nh * 2 + 1], ah[hh], bh[nh][2], bh[nh][3]);
                            mma16816(accH[hh][nh * 2 + 1], ah[hh], bl[nh][2], bl[nh][3]);
                            mma16816(accH[hh][nh * 2 + 1], al[hh], bh[nh][2], bh[nh][3]);
                        }
                }
            };
            stageH(0, 0);
            stageH(1, 1);
            cp_wait<1>();
            __syncwarp();
            compH(0, 0);
            stageH(2, 0);
            cp_wait<1>();
            __syncwarp();
            compH(1, 1);
            stageH(3, 1);
            cp_wait<1>();
            __syncwarp();
            compH(2, 0);
            stageH(4, 0);
            cp_wait<1>();
            __syncwarp();
            compH(3, 1);
            stageH(5, 1);
            cp_wait<1>();
            __syncwarp();
            compH(4, 0);
            cp_wait<0>();
            __syncwarp();
            compH(5, 1);
        } else {
            // =================== fma2 role: 2 chunks of 32 k ===================
#pragma unroll
            for (int i = 0; i < 4; i++)
#pragma unroll
                for (int j = 0; j < 8; j++) accF[i][j] = 0ull;

            auto stageF = [&](int c, int buf) {
                int kbase = 768 + (w - 4) * 64 + c * 32;
#pragma unroll
                for (int q = 0; q < 8; q++) {
                    int row = srow0 + 8 * (q & 3);
                    int c4 = sc4 + 4 * (q >> 2);
                    unsigned dst = afBase + (unsigned)(buf * 4608 + (row * 36 + c4 * 4) * 4);
                    cpasync16(dst, Hp + (size_t)(m0 + row) * HID + kbase + c4 * 4);
                }
                cp_commit();
            };
            auto compF = [&](int c, int buf) {
                unsigned aB = afBase + (unsigned)(buf * 4608);
                unsigned wK = smBase + (unsigned)(((w - 4) * 64 + c * 32) * 4);
#pragma unroll
                for (int kp = 0; kp < 16; kp++) {
                    unsigned kByte = (unsigned)kp * 8u;
                    unsigned long long a[4], wv[8];
#pragma unroll
                    for (int i = 0; i < 4; i++) a[i] = lds64(aB + aOff[i] + kByte);
#pragma unroll
                    for (int j = 0; j < 8; j++) wv[j] = lds64(wK + wOff[j] + kByte);
#pragma unroll
                    for (int i = 0; i < 4; i++)
#pragma unroll
                        for (int j = 0; j < 8; j++) fma2(accF[i][j], a[i], wv[j]);
                }
            };
            stageF(0, 0);
            stageF(1, 1);
            cp_wait<1>();
            __syncwarp();
            compF(0, 0);
            cp_wait<0>();
            __syncwarp();
            compF(1, 1);
        }

        __syncthreads();  // all warps done with A staging before aliasing as Rs

        // ---- write warp partials into Rs ----
        if (w < 4) {
#pragma unroll
            for (int hh = 0; hh < 2; hh++)
#pragma unroll
                for (int j = 0; j < 4; j++) {
                    int mrow = hh * 16 + (l >> 2);
                    int nc = j * 8 + 2 * (l & 3);
                    *(float2*)&Rs[(w * 32 + mrow) * RS_STRIDE + nc] =
                        make_float2(accH[hh][j][0], accH[hh][j][1]);
                    *(float2*)&Rs[(w * 32 + mrow + 8) * RS_STRIDE + nc] =
                        make_float2(accH[hh][j][2], accH[hh][j][3]);
                }
        } else {
#pragma unroll
            for (int i = 0; i < 4; i++) {
                int m = thrm + 8 * i;
#pragma unroll
                for (int j = 0; j < 8; j++) {
                    int n = thrn + 4 * j;
                    float lo, hi;
                    unpack2(accF[i][j], lo, hi);
                    Rs[(w * 32 + m) * RS_STRIDE + n] = lo + hi;
                }
            }
        }
        __syncthreads();

        // ---- vectorized reduce + prefetched xp + tanh.approx ----
        {
            float4 sum = make_float4(0.f, 0.f, 0.f, 0.f);
#pragma unroll
            for (int g = 0; g < 8; g++) {
                float4 v = *(float4*)&Rs[(g * 32 + mE) * RS_STRIDE + nqE];
                sum.x += v.x;
                sum.y += v.y;
                sum.z += v.z;
                sum.w += v.w;
            }
            float4 h;
            h.x = tanh_fast(xpE.x + sum.x);
            h.y = tanh_fast(xpE.y + sum.y);
            h.z = tanh_fast(xpE.z + sum.z);
            h.w = tanh_fast(xpE.w + sum.w);
            *(float4*)gpE = h;

            unsigned p01 = bf16x2pack(h.x, h.y);
            unsigned p23 = bf16x2pack(h.z, h.w);
            float r0 = h.x - bf16lo_as_f32(p01);
            float r1 = h.y - bf16hi_as_f32(p01);
            float r2 = h.z - bf16lo_as_f32(p23);
            float r3 = h.w - bf16hi_as_f32(p23);
            unsigned q01 = bf16x2pack(r0, r1);
            unsigned q23 = bf16x2pack(r2, r3);
            *(uint2*)&g_hseq[s + 1][0][m0 + mE][n0 + nqE] = make_uint2(p01, p23);
            *(uint2*)&g_hseq[s + 1][1][m0 + mE][n0 + nqE] = make_uint2(q01, q23);
        }

        __syncthreads();  // all writes program-ordered before the release below
        if (t == 0) {
            red_release_add(&g_bar[mi], 1u);  // release covers block writes (bar.sync HB)
            unsigned target = 32u * (unsigned)(s + 1);
            while (ld_acq(&g_bar[mi]) < target) __nanosleep(20);
        }
        __syncthreads();
    }
}

// ---------------- kernel 3: FC1 as 3-term bf16 HMMA GEMM ----------------
#define F1_B_OFF 0                      // B tiles: [2 buf][2 split][112 x 80B]
#define F1_BBUF 17920
#define F1_BSPL 8960
#define F1_A_OFF 35840                  // A: [8 warps][2 buf][2 split][16 x 80B]
#define F1_AWARP 5120
#define F1_W_OFF 76800                  // W stage fp32: [2 buf][104 x 144B]
#define F1_WBUF 14976
#define F1_SMEM 106752

__global__ __launch_bounds__(256, 2) void fc1_hmma(const float* __restrict__ W1) {
    extern __shared__ unsigned char smc[];
    unsigned smBase = smem_u32(smc);
    int s = blockIdx.x;
    int kh = blockIdx.y;  // k-half 0..1
    int t = threadIdx.x;
    int w = t >> 5, l = t & 31;
    int khbase = kh * 512;

    // zero pad rows 104..111 of all 4 B regions (once)
    for (int i = t; i < 640; i += 256) {
        int reg = i / 160, off = (i % 160) * 4;
        int b = reg >> 1, sp = reg & 1;
        *(unsigned*)(smc + F1_B_OFF + b * F1_BBUF + sp * F1_BSPL + 104 * 80 + off) = 0u;
    }
    __syncthreads();

    unsigned aLane = (unsigned)((l & 15) * 80 + (l >> 4) * 16);
    unsigned bLane = (unsigned)(((l >> 4) * 8 + (l & 7)) * 80 + ((l >> 3) & 1) * 16);
    unsigned aWarp = smBase + (unsigned)(F1_A_OFF + w * F1_AWARP);

    auto stage = [&](int c) {
        int buf = c & 1;
        int kc = khbase + c * 32;
#pragma unroll
        for (int sp = 0; sp < 2; sp++) {
#pragma unroll
            for (int q = 0; q < 2; q++) {
                int idx = l + q * 32;
                int row = idx >> 2, seg = idx & 3;
                cpasync16(aWarp + (unsigned)(buf * 2560 + sp * 1280 + row * 80 + seg * 16),
                          &g_hseq[s + 1][sp][w * 16 + row][kc + seg * 8]);
            }
        }
        for (int i = t; i < 832; i += 256) {
            int row = i >> 3, seg = i & 7;
            if (row < FC1N)
                cpasync16(smBase + (unsigned)(F1_W_OFF + buf * F1_WBUF + row * 144 + seg * 16),
                          W1 + (size_t)row * (SEQ * HID) + (size_t)s * HID + kc + seg * 4);
        }
        cp_commit();
    };

    auto convert = [&](int c) {
        int buf = c & 1;
        const unsigned char* ws = smc + F1_W_OFF + buf * F1_WBUF;
        unsigned char* bhi = smc + F1_B_OFF + buf * F1_BBUF;
        unsigned char* blo = bhi + F1_BSPL;
        for (int i = t; i < 832; i += 256) {
            int row = i >> 3, q = i & 7;
            float4 v = (row < FC1N) ? *(const float4*)(ws + row * 144 + q * 16)
                                    : make_float4(0.f, 0.f, 0.f, 0.f);
            unsigned p0 = bf16x2pack(v.x, v.y);
            unsigned p1 = bf16x2pack(v.z, v.w);
            float r0 = v.x - bf16lo_as_f32(p0);
            float r1 = v.y - bf16hi_as_f32(p0);
            float r2 = v.z - bf16lo_as_f32(p1);
            float r3 = v.w - bf16hi_as_f32(p1);
            unsigned q0 = bf16x2pack(r0, r1);
            unsigned q1 = bf16x2pack(r2, r3);
            *(uint2*)(bhi + row * 80 + q * 8) = make_uint2(p0, p1);
            *(uint2*)(blo + row * 80 + q * 8) = make_uint2(q0, q1);
        }
    };

    float acc[14][4];
#pragma unroll
    for (int j = 0; j < 14; j++)
#pragma unroll
        for (int c = 0; c < 4; c++) acc[j][c] = 0.0f;

    auto compute = [&](int c) {
        int buf = c & 1;
        unsigned aB = aWarp + (unsigned)(buf * 2560) + aLane;
        unsigned bB = smBase + (unsigned)(F1_B_OFF + buf * F1_BBUF) + bLane;
#pragma unroll
        for (int kk = 0; kk < 2; kk++) {
            unsigned ah[4], al[4];
            ldsm4(ah, aB + (unsigned)(kk * 32));
            ldsm4(al, aB + (unsigned)(1280 + kk * 32));
#pragma unroll
            for (int jt = 0; jt < 7; jt++) {
                unsigned bh[4], bl[4];
                ldsm4(bh, bB + (unsigned)(jt * 1280 + kk * 32));
                ldsm4(bl, bB + (unsigned)(F1_BSPL + jt * 1280 + kk * 32));
                mma16816(acc[2 * jt + 0], ah, bh[0], bh[1]);
                mma16816(acc[2 * jt + 0], ah, bl[0], bl[1]);
                mma16816(acc[2 * jt + 0], al, bh[0], bh[1]);
                mma16816(acc[2 * jt + 1], ah, bh[2], bh[3]);
                mma16816(acc[2 * jt + 1], ah, bl[2], bl[3]);
                mma16816(acc[2 * jt + 1], al, bh[2], bh[3]);
            }
        }
    };

    stage(0);
    stage(1);
#pragma unroll 1
    for (int c = 0; c < 16; c++) {
        if (c >= 14) cp_wait<0>(); else cp_wait<1>();
        __syncthreads();
        convert(c);
        __syncthreads();
        compute(c);
        if (c < 14) stage(c + 2);
    }

    float* dst = g_part + ((size_t)kh * SEQ + s) * BATCH * FC1N;
    int b0 = w * 16 + (l >> 2);
#pragma unroll
    for (int nt = 0; nt < 13; nt++) {
        int f0 = 8 * nt + 2 * (l & 3);
        if (f0 < FC1N) {
            *(float2*)&dst[(size_t)b0 * FC1N + f0] = make_float2(acc[nt][0], acc[nt][1]);
            *(float2*)&dst[(size_t)(b0 + 8) * FC1N + f0] = make_float2(acc[nt][2], acc[nt][3]);
        }
    }
}

// ---------------- kernel 4: deterministic reduce + bias + relu ----------------
__global__ __launch_bounds__(256) void reduce_kernel(const float* __restrict__ b1) {
    int i = blockIdx.x * 256 + threadIdx.x;
    if (i >= BATCH * FC1N) return;
    int f = i % FC1N;
    float p0 = 0.0f, p1 = 0.0f;
    for (int q = 0; q < 2 * SEQ; q += 2) {
        p0 += g_part[(size_t)q * BATCH * FC1N + i];
        p1 += g_part[(size_t)(q + 1) * BATCH * FC1N + i];
    }
    g_h1[i] = fmaxf(b1[f] + p0 + p1, 0.0f);
}

// ---------------- kernel 5: FC2 + log_softmax ----------------
__global__ __launch_bounds__(128) void fc2_kernel(const float* __restrict__ W2,
                                                  const float* __restrict__ b2,
                                                  float* __restrict__ out) {
    __shared__ float sW2[NCLS * FC1N];
    int t = threadIdx.x;
    for (int i = t; i < NCLS * FC1N; i += 128) sW2[i] = W2[i];
    __syncthreads();

    float hv[FC1N];
#pragma unroll
    for (int f = 0; f < FC1N; f++) hv[f] = g_h1[(size_t)t * FC1N + f];

    float logits[NCLS];
#pragma unroll
    for (int c = 0; c < NCLS; c++) {
        float acc = b2[c];
#pragma unroll
        for (int f = 0; f < FC1N; f++) acc += hv[f] * sW2[c * FC1N + f];
        logits[c] = acc;
    }
    float m = logits[0];
#pragma unroll
    for (int c = 1; c < NCLS; c++) m = fmaxf(m, logits[c]);
    float sum = 0.0f;
#pragma unroll
    for (int c = 0; c < NCLS; c++) sum += expf(logits[c] - m);
    float lse = m + logf(sum);
#pragma unroll
    for (int c = 0; c < NCLS; c++) out[(size_t)t * NCLS + c] = logits[c] - lse;
}

// ---------------- launch ----------------
extern "C" void kernel_launch(void* const* d_in, const int* in_sizes, int n_in,
                              void* d_out, int out_size) {
    const float* x = (const float*)d_in[0];
    const float* h0 = (const float*)d_in[1];
    const float* Wih = (const float*)d_in[2];
    const float* Whh = (const float*)d_in[3];
    const float* bih = (const float*)d_in[4];
    const float* bhh = (const float*)d_in[5];
    const float* W1 = (const float*)d_in[6];
    const float* b1 = (const float*)d_in[7];
    const float* W2 = (const float*)d_in[8];
    const float* b2 = (const float*)d_in[9];
    float* out = (float*)d_out;
    (void)in_sizes; (void)n_in; (void)out_size;

    cudaFuncSetAttribute(rnn_dual, cudaFuncAttributeMaxDynamicSharedMemorySize,
                         SCAN_SMEM);
    cudaFuncSetAttribute(fc1_hmma, cudaFuncAttributeMaxDynamicSharedMemorySize,
                         F1_SMEM);

    xproj_kernel<<<dim3(HID / XP_BN, (SEQ * BATCH) / XP_BM), 256>>>(x, Wih, bih, bhh);
    h0cvt_kernel<<<(BATCH * HID + 255) / 256, 256>>>(h0);
    rnn_dual<<<dim3(32, 4), 256, SCAN_SMEM>>>(h0, Whh);
    fc1_hmma<<<dim3(SEQ, 2), 256, F1_SMEM>>>(W1);
    reduce_kernel<<<(BATCH * FC1N + 255) / 256, 256>>>(b1);
    fc2_kernel<<<1, 128>>>(W2, b2, out);
}